// round 6
// baseline (speedup 1.0000x reference)
#include <cuda_runtime.h>
#include <cuda_fp16.h>
#include <cstdint>

#define T_ 7
#define NTOK 36864            // B*H*W
#define ROWS (T_ * NTOK)      // 258048
#define CDIM 256
#define NQKV 768

// Scratch (device globals — no allocation allowed)
__device__ __half g_a_h[(size_t)ROWS * CDIM];    // frames, fp16
__device__ __half g_qkv_h[(size_t)ROWS * NQKV];  // [t*NTOK+s][q|k|v], fp16
__device__ __half g_ctx_h[(size_t)ROWS * CDIM];  // attn out, fp16
__device__ __half g_wbt_h[NQKV * CDIM];          // [n][k], fp16
__device__ __half g_wot_h[CDIM * CDIM];          // [c][nd], fp16
__device__ float  g_bias[T_ * NQKV];

// ---------------------------------------------------------------------------
// Portable PTX helpers (compute_103 virtual arch — no tcgen05/TMA-tensor)
// ---------------------------------------------------------------------------
__device__ __forceinline__ uint32_t smem_u32(const void* p) {
    uint32_t a;
    asm("{ .reg .u64 t; cvta.to.shared.u64 t, %1; cvt.u32.u64 %0, t; }" : "=r"(a) : "l"(p));
    return a;
}
__device__ __forceinline__ void ldsm4(uint32_t* r, uint32_t addr) {
    asm volatile("ldmatrix.sync.aligned.m8n8.x4.shared.b16 {%0,%1,%2,%3}, [%4];"
        : "=r"(r[0]), "=r"(r[1]), "=r"(r[2]), "=r"(r[3]) : "r"(addr));
}
__device__ __forceinline__ void mma_f16(float* d, const uint32_t* a, const uint32_t* b) {
    asm volatile("mma.sync.aligned.m16n8k16.row.col.f32.f16.f16.f32 "
        "{%0,%1,%2,%3}, {%4,%5,%6,%7}, {%8,%9}, {%0,%1,%2,%3};"
        : "+f"(d[0]), "+f"(d[1]), "+f"(d[2]), "+f"(d[3])
        : "r"(a[0]), "r"(a[1]), "r"(a[2]), "r"(a[3]), "r"(b[0]), "r"(b[1]));
}
#define CP_ASYNC16(dst, src) asm volatile("cp.async.cg.shared.global [%0], [%1], 16;" :: "r"(dst), "l"(src))
#define CP_COMMIT()          asm volatile("cp.async.commit_group;" ::: "memory")
#define CP_WAIT1()           asm volatile("cp.async.wait_group 1;" ::: "memory")
#define CP_WAIT0()           asm volatile("cp.async.wait_group 0;" ::: "memory")

__device__ __forceinline__ uint2 f4_to_h4(float4 v) {
    __half2 h0 = __float22half2_rn(make_float2(v.x, v.y));
    __half2 h1 = __float22half2_rn(make_float2(v.z, v.w));
    uint2 r;
    r.x = *reinterpret_cast<uint32_t*>(&h0);
    r.y = *reinterpret_cast<uint32_t*>(&h1);
    return r;
}
__device__ __forceinline__ float4 h4_to_f4(uint2 u) {
    __half2 h0 = *reinterpret_cast<__half2*>(&u.x);
    __half2 h1 = *reinterpret_cast<__half2*>(&u.y);
    float2 a = __half22float2(h0), b = __half22float2(h1);
    return make_float4(a.x, a.y, b.x, b.y);
}

#define STAGE_BYTES 24576u    // A 16KB (128x64 fp16) + B 8KB (64x64 fp16)
#define SM_TOTAL (3 * STAGE_BYTES)   // 73728/CTA -> 3 CTAs/SM (216KB < 227KB)

// ---------------------------------------------------------------------------
// Prep kernels
// ---------------------------------------------------------------------------
__global__ void prep_frames_kernel(const float* __restrict__ frames) {
    size_t i = (size_t)blockIdx.x * blockDim.x + threadIdx.x;   // float4 slot
    const float4 v = reinterpret_cast<const float4*>(frames)[i];
    reinterpret_cast<uint2*>(g_a_h)[i] = f4_to_h4(v);
}

__global__ void prep_wt_kernel(const float* __restrict__ Wq,
                               const float* __restrict__ Wk,
                               const float* __restrict__ Wv,
                               const float* __restrict__ Wo) {
    int i = blockIdx.x * blockDim.x + threadIdx.x;
    if (i < NQKV * CDIM) {
        int n = i / CDIM, c = i % CDIM;
        float v;
        if (n < 256)      v = Wq[c * 256 + n];
        else if (n < 512) v = Wk[c * 256 + (n - 256)];
        else              v = Wv[c * 256 + (n - 512)];
        g_wbt_h[i] = __float2half_rn(v);
    } else if (i < NQKV * CDIM + CDIM * CDIM) {
        int j = i - NQKV * CDIM;
        int co = j / CDIM, nd = j % CDIM;
        g_wot_h[j] = __float2half_rn(Wo[nd * 256 + co]);
    }
}

__global__ void prep_bias_kernel(const float* __restrict__ te,
                                 const float* __restrict__ Wq,
                                 const float* __restrict__ bq,
                                 const float* __restrict__ Wk,
                                 const float* __restrict__ bk,
                                 const float* __restrict__ bv) {
    int i = blockIdx.x * blockDim.x + threadIdx.x;
    if (i >= T_ * NQKV) return;
    int t = i / NQKV, n = i % NQKV;
    float r;
    if (n < 512) {
        const float* W = (n < 256) ? Wq : Wk;
        int nn = n & 255;
        float acc = (n < 256) ? bq[nn] : bk[nn];
        for (int c = 0; c < CDIM; c++) acc += te[t * CDIM + c] * W[c * 256 + nn];
        r = acc;
    } else {
        r = bv[n - 512];
    }
    g_bias[i] = r;
}

// ---------------------------------------------------------------------------
// fp16 mma.sync GEMM: C[row][n] = A[row][k] * Bt[n][k] + bias
// CTA 128(M) x 64(N), K=256 in 4 chunks of 64, 3-stage cp.async pipeline.
// 8 warps, warp tile 32x32 (2m x 4n of m16n8k16) -> acc 32 regs/thread.
// __launch_bounds__(256,3): <=85 regs, 72KB smem -> 3 CTAs (24 warps) per SM.
// Epilogue: bias pre-loaded into regs, fp16 (or f32) smem stage, coalesced out.
// ---------------------------------------------------------------------------
template<int NW, int TSTRIDE, bool OUT_HALF>
__global__ __launch_bounds__(256, 3)
void gemm_h_kernel(const __half* __restrict__ A,
                   const __half* __restrict__ Bt,
                   const float* __restrict__ bias,
                   void* __restrict__ Cout) {
    extern __shared__ __align__(128) char smem[];
    const uint32_t sb = smem_u32(smem);

    const int tid  = threadIdx.x;
    const int lane = tid & 31, wid = tid >> 5;
    const int wm = wid >> 1;          // 0..3 : rows wm*32
    const int wn = wid & 1;           // 0..1 : cols wn*32
    const int row0 = blockIdx.y * 128;
    const int col0 = blockIdx.x * 64;

    // Fragment addressing (SW128 xor; smem rows are 64 fp16 = 128B)
    const uint32_t fxor  = (uint32_t)(lane & 7) << 4;
    const uint32_t a_row = (uint32_t)(wm * 32 + (lane & 15)) * 128;
    const uint32_t ahalf = (uint32_t)(lane >> 4) * 16;
    const uint32_t b_row = (uint32_t)(wn * 32 + (lane & 7) + ((lane >> 4) << 3)) * 128;
    const uint32_t bhalf = (uint32_t)((lane >> 3) & 1) * 16;

    auto stageA = [&](int kc, uint32_t nb) {
        #pragma unroll
        for (int i = 0; i < 4; i++) {
            int g = tid + i * 256;                 // 1024 granules (128 rows x 8)
            int r = g >> 3, c16 = g & 7;
            uint32_t dst = nb + (uint32_t)r * 128 + (((uint32_t)c16 * 16) ^ (((uint32_t)(r & 7)) << 4));
            const __half* src = A + (size_t)(row0 + r) * CDIM + kc * 64 + c16 * 8;
            CP_ASYNC16(dst, src);
        }
    };
    auto stageB = [&](int kc, uint32_t nb) {
        #pragma unroll
        for (int i = 0; i < 2; i++) {
            int g = tid + i * 256;                 // 512 granules (64 rows x 8)
            int r = g >> 3, c16 = g & 7;
            uint32_t dst = nb + 16384u + (uint32_t)r * 128 + (((uint32_t)c16 * 16) ^ (((uint32_t)(r & 7)) << 4));
            const __half* src = Bt + (size_t)(col0 + r) * CDIM + kc * 64 + c16 * 8;
            CP_ASYNC16(dst, src);
        }
    };

    // prologue: stage chunks 0, 1
    stageA(0, sb);               stageB(0, sb);               CP_COMMIT();
    stageA(1, sb + STAGE_BYTES); stageB(1, sb + STAGE_BYTES); CP_COMMIT();

    float acc[2][4][4];
    #pragma unroll
    for (int mt = 0; mt < 2; mt++)
        #pragma unroll
        for (int nt = 0; nt < 4; nt++)
            #pragma unroll
            for (int e = 0; e < 4; e++) acc[mt][nt][e] = 0.0f;

    #pragma unroll 1
    for (int kc = 0; kc < 4; kc++) {
        const uint32_t sbase = sb + (uint32_t)(kc % 3) * STAGE_BYTES;
        if (kc == 3) { CP_WAIT0(); } else { CP_WAIT1(); }
        __syncthreads();

        #pragma unroll
        for (int ks = 0; ks < 4; ks++) {
            uint32_t af[2][4];
            #pragma unroll
            for (int mt = 0; mt < 2; mt++)
                ldsm4(af[mt], sbase + a_row + (uint32_t)mt * 2048 + ((ahalf + ks * 32) ^ fxor));
            uint32_t bf[2][4];
            #pragma unroll
            for (int np = 0; np < 2; np++)
                ldsm4(bf[np], sbase + 16384u + b_row + (uint32_t)np * 2048 + ((bhalf + ks * 32) ^ fxor));
            #pragma unroll
            for (int mt = 0; mt < 2; mt++)
                #pragma unroll
                for (int nt = 0; nt < 4; nt++)
                    mma_f16(acc[mt][nt], af[mt], &bf[nt >> 1][(nt & 1) * 2]);
        }

        if (kc < 2) {
            const uint32_t nb = sb + (uint32_t)((kc + 2) % 3) * STAGE_BYTES;
            stageA(kc + 2, nb);
            stageB(kc + 2, nb);
            CP_COMMIT();
        }
    }
    __syncthreads();

    // ---- epilogue: bias in regs -> smem stage -> coalesced stores ----
    const int t = TSTRIDE ? (blockIdx.y / 288) : 0;
    float2 br[4];
    #pragma unroll
    for (int nt = 0; nt < 4; nt++)
        br[nt] = *reinterpret_cast<const float2*>(
            bias + t * TSTRIDE + col0 + wn * 32 + nt * 8 + (lane & 3) * 2);

    if (OUT_HALF) {
        __half* Hs = reinterpret_cast<__half*>(smem);   // [128][72] = 18KB
        #pragma unroll
        for (int mt = 0; mt < 2; mt++) {
            const int r0 = wm * 32 + mt * 16 + (lane >> 2);
            #pragma unroll
            for (int nt = 0; nt < 4; nt++) {
                const int c0 = wn * 32 + nt * 8 + (lane & 3) * 2;
                __half2 v0 = __float22half2_rn(make_float2(acc[mt][nt][0] + br[nt].x,
                                                           acc[mt][nt][1] + br[nt].y));
                __half2 v1 = __float22half2_rn(make_float2(acc[mt][nt][2] + br[nt].x,
                                                           acc[mt][nt][3] + br[nt].y));
                *reinterpret_cast<__half2*>(Hs + r0 * 72 + c0)       = v0;
                *reinterpret_cast<__half2*>(Hs + (r0 + 8) * 72 + c0) = v1;
            }
        }
        __syncthreads();
        __half* outp = reinterpret_cast<__half*>(Cout);
        #pragma unroll
        for (int i = 0; i < 4; i++) {
            int id = tid + i * 256;                 // 1024 uint4 slots (16KB)
            int r = id >> 3, c = (id & 7) * 8;
            uint4 v = *reinterpret_cast<const uint4*>(Hs + r * 72 + c);
            *reinterpret_cast<uint4*>(outp + (size_t)(row0 + r) * NW + col0 + c) = v;
        }
    } else {
        float* Cs = reinterpret_cast<float*>(smem);     // [128][68] = 34.8KB
        #pragma unroll
        for (int mt = 0; mt < 2; mt++) {
            const int r0 = wm * 32 + mt * 16 + (lane >> 2);
            #pragma unroll
            for (int nt = 0; nt < 4; nt++) {
                const int c0 = wn * 32 + nt * 8 + (lane & 3) * 2;
                *reinterpret_cast<float2*>(Cs + r0 * 68 + c0) =
                    make_float2(acc[mt][nt][0] + br[nt].x, acc[mt][nt][1] + br[nt].y);
                *reinterpret_cast<float2*>(Cs + (r0 + 8) * 68 + c0) =
                    make_float2(acc[mt][nt][2] + br[nt].x, acc[mt][nt][3] + br[nt].y);
            }
        }
        __syncthreads();
        float* outp = reinterpret_cast<float*>(Cout);
        #pragma unroll
        for (int i = 0; i < 8; i++) {
            int id = tid + i * 256;                 // 2048 float4 slots (32KB)
            int r = id >> 4, c = (id & 15) * 4;
            float4 v = *reinterpret_cast<const float4*>(Cs + r * 68 + c);
            *reinterpret_cast<float4*>(outp + (size_t)(row0 + r) * NW + col0 + c) = v;
        }
    }
}

// ---------------------------------------------------------------------------
// Attention over T=7 per (token, 4-head group), fp16 in / fp16 out.
// ---------------------------------------------------------------------------
__global__ void attn_kernel() {
    const int gw = (blockIdx.x * blockDim.x + threadIdx.x) >> 5;
    const int lane = threadIdx.x & 31;
    const int s = gw >> 1;
    const int half = gw & 1;
    const int hg = lane >> 3, dg = lane & 7;
    const int col = (half * 4 + hg) * 32 + dg * 4;

    float4 q[7], k[7], v[7];
    #pragma unroll
    for (int t = 0; t < 7; t++) {
        const __half* base = g_qkv_h + (size_t)(t * NTOK + s) * NQKV;
        q[t] = h4_to_f4(*reinterpret_cast<const uint2*>(base + col));
        k[t] = h4_to_f4(*reinterpret_cast<const uint2*>(base + 256 + col));
        v[t] = h4_to_f4(*reinterpret_cast<const uint2*>(base + 512 + col));
    }

    const float scale = 0.17677669529663687f;  // 1/sqrt(32)
    float e[7] = {0.f, 0.f, 0.f, 0.f, 0.f, 0.f, 0.f};
    #pragma unroll
    for (int qt = 0; qt < 7; qt++) {
        #pragma unroll
        for (int t = 0; t < 7; t++) {
            float d = q[qt].x * k[t].x + q[qt].y * k[t].y
                    + q[qt].z * k[t].z + q[qt].w * k[t].w;
            d += __shfl_xor_sync(0xffffffffu, d, 1);
            d += __shfl_xor_sync(0xffffffffu, d, 2);
            d += __shfl_xor_sync(0xffffffffu, d, 4);
            const int p = qt * 7 + t;
            if ((p & 7) == dg) e[p >> 3] = __expf(d * scale);
        }
    }

    float4 ctx[7];
    float den[7];
    #pragma unroll
    for (int qt = 0; qt < 7; qt++) { ctx[qt] = make_float4(0, 0, 0, 0); den[qt] = 0.f; }
    #pragma unroll
    for (int qt = 0; qt < 7; qt++) {
        #pragma unroll
        for (int t = 0; t < 7; t++) {
            const int p = qt * 7 + t;
            float eb = __shfl_sync(0xffffffffu, e[p >> 3], p & 7, 8);
            den[qt] += eb;
            ctx[qt].x += eb * v[t].x;
            ctx[qt].y += eb * v[t].y;
            ctx[qt].z += eb * v[t].z;
            ctx[qt].w += eb * v[t].w;
        }
    }
    #pragma unroll
    for (int qt = 0; qt < 7; qt++) {
        const float r = 1.0f / den[qt];
        float4 o = make_float4(ctx[qt].x * r, ctx[qt].y * r, ctx[qt].z * r, ctx[qt].w * r);
        *reinterpret_cast<uint2*>(g_ctx_h + (size_t)(qt * NTOK + s) * CDIM + col) = f4_to_h4(o);
    }
}

// ---------------------------------------------------------------------------
extern "C" void kernel_launch(void* const* d_in, const int* /*in_sizes*/, int /*n_in*/,
                              void* d_out, int /*out_size*/) {
    const float* frames = (const float*)d_in[0];
    const float* temb   = (const float*)d_in[1];
    const float* Wq     = (const float*)d_in[2];
    const float* bq     = (const float*)d_in[3];
    const float* Wk     = (const float*)d_in[4];
    const float* bk     = (const float*)d_in[5];
    const float* Wv     = (const float*)d_in[6];
    const float* bv     = (const float*)d_in[7];
    const float* Wo     = (const float*)d_in[8];
    const float* bo     = (const float*)d_in[9];
    float* out = (float*)d_out;

    void *p_ah, *p_qkv, *p_ctx, *p_wbt, *p_wot, *p_bias;
    cudaGetSymbolAddress(&p_ah,   g_a_h);
    cudaGetSymbolAddress(&p_qkv,  g_qkv_h);
    cudaGetSymbolAddress(&p_ctx,  g_ctx_h);
    cudaGetSymbolAddress(&p_wbt,  g_wbt_h);
    cudaGetSymbolAddress(&p_wot,  g_wot_h);
    cudaGetSymbolAddress(&p_bias, g_bias);

    cudaFuncSetAttribute(gemm_h_kernel<NQKV, NQKV, true>,
                         cudaFuncAttributeMaxDynamicSharedMemorySize, SM_TOTAL);
    cudaFuncSetAttribute(gemm_h_kernel<CDIM, 0, false>,
                         cudaFuncAttributeMaxDynamicSharedMemorySize, SM_TOTAL);

    prep_wt_kernel<<<(NQKV * CDIM + CDIM * CDIM + 255) / 256, 256>>>(Wq, Wk, Wv, Wo);
    prep_bias_kernel<<<(T_ * NQKV + 255) / 256, 256>>>(temb, Wq, bq, Wk, bk, bv);
    prep_frames_kernel<<<(ROWS * CDIM / 4) / 256, 256>>>(frames);

    // QKV projection: [258048 x 256] @ [256 x 768] + bias[t]  -> fp16 qkv
    gemm_h_kernel<NQKV, NQKV, true><<<dim3(12, ROWS / 128), 256, SM_TOTAL>>>(
        (const __half*)p_ah, (const __half*)p_wbt, (const float*)p_bias, p_qkv);

    // Attention (fp16 -> fp16)
    attn_kernel<<<(NTOK * 2 * 32) / 256, 256>>>();

    // Output projection: [258048 x 256] @ [256 x 256] + bo -> f32 out
    gemm_h_kernel<CDIM, 0, false><<<dim3(4, ROWS / 128), 256, SM_TOTAL>>>(
        (const __half*)p_ctx, (const __half*)p_wot, bo, out);
}

// round 7
// speedup vs baseline: 1.0129x; 1.0129x over previous
#include <cuda_runtime.h>
#include <cuda_fp16.h>
#include <cstdint>

#define T_ 7
#define NTOK 36864            // B*H*W
#define ROWS (T_ * NTOK)      // 258048
#define CDIM 256
#define NQKV 768

// Scratch (device globals — no allocation allowed)
__device__ __half g_a_h[(size_t)ROWS * CDIM];    // frames, fp16
__device__ __half g_qkv_h[(size_t)ROWS * NQKV];  // [t*NTOK+s][q|k|v], fp16
__device__ __half g_ctx_h[(size_t)ROWS * CDIM];  // attn out, fp16
__device__ __half g_wbt_h[NQKV * CDIM];          // [n][k], fp16
__device__ __half g_wot_h[CDIM * CDIM];          // [c][nd], fp16
__device__ float  g_bias[T_ * NQKV];

// ---------------------------------------------------------------------------
// Portable PTX helpers (compute_103 virtual arch — no tcgen05/TMA-tensor)
// ---------------------------------------------------------------------------
__device__ __forceinline__ uint32_t smem_u32(const void* p) {
    uint32_t a;
    asm("{ .reg .u64 t; cvta.to.shared.u64 t, %1; cvt.u32.u64 %0, t; }" : "=r"(a) : "l"(p));
    return a;
}
__device__ __forceinline__ void ldsm4(uint32_t* r, uint32_t addr) {
    asm volatile("ldmatrix.sync.aligned.m8n8.x4.shared.b16 {%0,%1,%2,%3}, [%4];"
        : "=r"(r[0]), "=r"(r[1]), "=r"(r[2]), "=r"(r[3]) : "r"(addr));
}
__device__ __forceinline__ void mma_f16(float* d, const uint32_t* a, const uint32_t* b) {
    asm volatile("mma.sync.aligned.m16n8k16.row.col.f32.f16.f16.f32 "
        "{%0,%1,%2,%3}, {%4,%5,%6,%7}, {%8,%9}, {%0,%1,%2,%3};"
        : "+f"(d[0]), "+f"(d[1]), "+f"(d[2]), "+f"(d[3])
        : "r"(a[0]), "r"(a[1]), "r"(a[2]), "r"(a[3]), "r"(b[0]), "r"(b[1]));
}
#define CP_ASYNC16(dst, src) asm volatile("cp.async.cg.shared.global [%0], [%1], 16;" :: "r"(dst), "l"(src))
#define CP_COMMIT()          asm volatile("cp.async.commit_group;" ::: "memory")
#define CP_WAIT1()           asm volatile("cp.async.wait_group 1;" ::: "memory")
#define CP_WAIT0()           asm volatile("cp.async.wait_group 0;" ::: "memory")

__device__ __forceinline__ uint2 f4_to_h4(float4 v) {
    __half2 h0 = __float22half2_rn(make_float2(v.x, v.y));
    __half2 h1 = __float22half2_rn(make_float2(v.z, v.w));
    uint2 r;
    r.x = *reinterpret_cast<uint32_t*>(&h0);
    r.y = *reinterpret_cast<uint32_t*>(&h1);
    return r;
}
__device__ __forceinline__ float4 h4_to_f4(uint2 u) {
    __half2 h0 = *reinterpret_cast<__half2*>(&u.x);
    __half2 h1 = *reinterpret_cast<__half2*>(&u.y);
    float2 a = __half22float2(h0), b = __half22float2(h1);
    return make_float4(a.x, a.y, b.x, b.y);
}

// Stage: A 128x32 fp16 (8KB, 64B rows) + B 128x32 fp16 (8KB) = 16KB
#define STAGE_BYTES 16384u
#define SM_TOTAL (3 * STAGE_BYTES)   // 49152/CTA -> 3 CTAs/SM (144KB)
// Smem row = 32 fp16 = 64B = 4 x 16B chunks. Swizzled chunk = ((r>>1)+c)&3:
// conflict-free for both cp.async stores and ldmatrix 8-row phases, and
// invariant under the mt/np row offsets (multiples of 16 -> (r>>1) += 0 mod 4... 8 ≡ 0 mod 4).

// ---------------------------------------------------------------------------
// Prep kernels
// ---------------------------------------------------------------------------
__global__ void prep_frames_kernel(const float* __restrict__ frames) {
    size_t i = (size_t)blockIdx.x * blockDim.x + threadIdx.x;   // float4 slot
    const float4 v = reinterpret_cast<const float4*>(frames)[i];
    reinterpret_cast<uint2*>(g_a_h)[i] = f4_to_h4(v);
}

__global__ void prep_wt_kernel(const float* __restrict__ Wq,
                               const float* __restrict__ Wk,
                               const float* __restrict__ Wv,
                               const float* __restrict__ Wo) {
    int i = blockIdx.x * blockDim.x + threadIdx.x;
    if (i < NQKV * CDIM) {
        int n = i / CDIM, c = i % CDIM;
        float v;
        if (n < 256)      v = Wq[c * 256 + n];
        else if (n < 512) v = Wk[c * 256 + (n - 256)];
        else              v = Wv[c * 256 + (n - 512)];
        g_wbt_h[i] = __float2half_rn(v);
    } else if (i < NQKV * CDIM + CDIM * CDIM) {
        int j = i - NQKV * CDIM;
        int co = j / CDIM, nd = j % CDIM;
        g_wot_h[j] = __float2half_rn(Wo[nd * 256 + co]);
    }
}

__global__ void prep_bias_kernel(const float* __restrict__ te,
                                 const float* __restrict__ Wq,
                                 const float* __restrict__ bq,
                                 const float* __restrict__ Wk,
                                 const float* __restrict__ bk,
                                 const float* __restrict__ bv) {
    int i = blockIdx.x * blockDim.x + threadIdx.x;
    if (i >= T_ * NQKV) return;
    int t = i / NQKV, n = i % NQKV;
    float r;
    if (n < 512) {
        const float* W = (n < 256) ? Wq : Wk;
        int nn = n & 255;
        float acc = (n < 256) ? bq[nn] : bk[nn];
        for (int c = 0; c < CDIM; c++) acc += te[t * CDIM + c] * W[c * 256 + nn];
        r = acc;
    } else {
        r = bv[n - 512];
    }
    g_bias[i] = r;
}

// ---------------------------------------------------------------------------
// fp16 mma.sync GEMM: C[row][n] = A[row][k] * Bt[n][k] + bias
// CTA 128(M) x 128(N), 128 threads = 4 warps (2m x 2n), warp tile 64x64
// (4m x 8n of m16n8k16): 8 ldsm per 32 mma (best LDSM:MMA ratio).
// K=256 in 8 chunks of 32, 3-stage cp.async pipeline.
// __launch_bounds__(128,3): 3 CTAs/SM (12 warps, 144KB smem, ~168 regs).
// ---------------------------------------------------------------------------
template<int NW, int TSTRIDE, bool OUT_HALF>
__global__ __launch_bounds__(128, 3)
void gemm_h_kernel(const __half* __restrict__ A,
                   const __half* __restrict__ Bt,
                   const float* __restrict__ bias,
                   void* __restrict__ Cout) {
    extern __shared__ __align__(128) char smem[];
    const uint32_t sb = smem_u32(smem);

    const int tid  = threadIdx.x;
    const int lane = tid & 31, wid = tid >> 5;
    const int wm = wid >> 1;          // 0..1 : rows wm*64
    const int wn = wid & 1;           // 0..1 : cols wn*64
    const int row0 = blockIdx.y * 128;
    const int col0 = blockIdx.x * 128;

    // Fragment row bases
    const int ar  = wm * 64 + (lane & 15);                       // A row
    const int ah  = lane >> 4;                                   // A 16B half
    const int brr = wn * 64 + (lane & 7) + ((lane >> 4) << 3);   // B row
    const int bh  = (lane >> 3) & 1;                             // B 16B half
    const uint32_t a_base = (uint32_t)ar * 64;
    const uint32_t b_base = 8192u + (uint32_t)brr * 64;
    const int a_sw = (ar >> 1) + ah;      // + 2*ks, &3, <<4
    const int b_sw = (brr >> 1) + bh;

    auto stage = [&](int kc, uint32_t nb) {
        #pragma unroll
        for (int i = 0; i < 4; i++) {
            int g = tid + i * 128;                 // 512 granules: 128 rows x 4
            int r = g >> 2, c = g & 3;
            uint32_t sw = (uint32_t)((((r >> 1) + c) & 3) << 4);
            CP_ASYNC16(nb + (uint32_t)r * 64 + sw,
                       A + (size_t)(row0 + r) * CDIM + kc * 32 + c * 8);
        }
        #pragma unroll
        for (int i = 0; i < 4; i++) {
            int g = tid + i * 128;
            int r = g >> 2, c = g & 3;
            uint32_t sw = (uint32_t)((((r >> 1) + c) & 3) << 4);
            CP_ASYNC16(nb + 8192u + (uint32_t)r * 64 + sw,
                       Bt + (size_t)(col0 + r) * CDIM + kc * 32 + c * 8);
        }
    };

    // prologue: stage chunks 0, 1
    stage(0, sb);               CP_COMMIT();
    stage(1, sb + STAGE_BYTES); CP_COMMIT();

    float acc[4][8][4];
    #pragma unroll
    for (int mt = 0; mt < 4; mt++)
        #pragma unroll
        for (int nt = 0; nt < 8; nt++)
            #pragma unroll
            for (int e = 0; e < 4; e++) acc[mt][nt][e] = 0.0f;

    #pragma unroll 1
    for (int kc = 0; kc < 8; kc++) {
        const uint32_t sbase = sb + (uint32_t)(kc % 3) * STAGE_BYTES;
        if (kc == 7) { CP_WAIT0(); } else { CP_WAIT1(); }
        __syncthreads();

        #pragma unroll
        for (int ks = 0; ks < 2; ks++) {
            const uint32_t aoff = (uint32_t)(((a_sw + 2 * ks) & 3) << 4);
            const uint32_t boff = (uint32_t)(((b_sw + 2 * ks) & 3) << 4);
            uint32_t af[4][4];
            #pragma unroll
            for (int mt = 0; mt < 4; mt++)
                ldsm4(af[mt], sbase + a_base + (uint32_t)mt * 1024 + aoff);
            uint32_t bf[4][4];
            #pragma unroll
            for (int np = 0; np < 4; np++)
                ldsm4(bf[np], sbase + b_base + (uint32_t)np * 1024 + boff);
            #pragma unroll
            for (int mt = 0; mt < 4; mt++)
                #pragma unroll
                for (int nt = 0; nt < 8; nt++)
                    mma_f16(acc[mt][nt], af[mt], &bf[nt >> 1][(nt & 1) * 2]);
        }

        if (kc < 6) {
            stage(kc + 2, sb + (uint32_t)((kc + 2) % 3) * STAGE_BYTES);
            CP_COMMIT();
        }
    }
    __syncthreads();

    // ---- epilogue: bias in regs; 2 passes of 64 rows via f32 smem stage ----
    const int t = TSTRIDE ? (blockIdx.y / 288) : 0;
    float2 br[8];
    #pragma unroll
    for (int nt = 0; nt < 8; nt++)
        br[nt] = *reinterpret_cast<const float2*>(
            bias + t * TSTRIDE + col0 + wn * 64 + nt * 8 + (lane & 3) * 2);

    float* Cs = reinterpret_cast<float*>(smem);   // [64][132] = 33.8KB
    #pragma unroll 1
    for (int p = 0; p < 2; p++) {
        if (wm == p) {
            #pragma unroll
            for (int mt = 0; mt < 4; mt++) {
                const int r0 = mt * 16 + (lane >> 2);
                #pragma unroll
                for (int nt = 0; nt < 8; nt++) {
                    const int c0 = wn * 64 + nt * 8 + (lane & 3) * 2;
                    *reinterpret_cast<float2*>(Cs + r0 * 132 + c0) =
                        make_float2(acc[mt][nt][0] + br[nt].x, acc[mt][nt][1] + br[nt].y);
                    *reinterpret_cast<float2*>(Cs + (r0 + 8) * 132 + c0) =
                        make_float2(acc[mt][nt][2] + br[nt].x, acc[mt][nt][3] + br[nt].y);
                }
            }
        }
        __syncthreads();
        if (OUT_HALF) {
            __half* outp = reinterpret_cast<__half*>(Cout);
            #pragma unroll
            for (int i = 0; i < 8; i++) {
                int id = tid + i * 128;            // 1024 slots: 64 rows x 16
                int r = id >> 4, c = (id & 15) * 8;
                float4 v0 = *reinterpret_cast<const float4*>(Cs + r * 132 + c);
                float4 v1 = *reinterpret_cast<const float4*>(Cs + r * 132 + c + 4);
                uint2 h0 = f4_to_h4(v0), h1 = f4_to_h4(v1);
                uint4 o = make_uint4(h0.x, h0.y, h1.x, h1.y);
                *reinterpret_cast<uint4*>(outp + (size_t)(row0 + p * 64 + r) * NW + col0 + c) = o;
            }
        } else {
            float* outp = reinterpret_cast<float*>(Cout);
            #pragma unroll
            for (int i = 0; i < 16; i++) {
                int id = tid + i * 128;            // 2048 slots: 64 rows x 32
                int r = id >> 5, c = (id & 31) * 4;
                float4 v = *reinterpret_cast<const float4*>(Cs + r * 132 + c);
                *reinterpret_cast<float4*>(outp + (size_t)(row0 + p * 64 + r) * NW + col0 + c) = v;
            }
        }
        __syncthreads();
    }
}

// ---------------------------------------------------------------------------
// Attention over T=7 per (token, 4-head group), fp16 in / fp16 out.
// ---------------------------------------------------------------------------
__global__ void attn_kernel() {
    const int gw = (blockIdx.x * blockDim.x + threadIdx.x) >> 5;
    const int lane = threadIdx.x & 31;
    const int s = gw >> 1;
    const int half = gw & 1;
    const int hg = lane >> 3, dg = lane & 7;
    const int col = (half * 4 + hg) * 32 + dg * 4;

    float4 q[7], k[7], v[7];
    #pragma unroll
    for (int t = 0; t < 7; t++) {
        const __half* base = g_qkv_h + (size_t)(t * NTOK + s) * NQKV;
        q[t] = h4_to_f4(*reinterpret_cast<const uint2*>(base + col));
        k[t] = h4_to_f4(*reinterpret_cast<const uint2*>(base + 256 + col));
        v[t] = h4_to_f4(*reinterpret_cast<const uint2*>(base + 512 + col));
    }

    const float scale = 0.17677669529663687f;  // 1/sqrt(32)
    float e[7] = {0.f, 0.f, 0.f, 0.f, 0.f, 0.f, 0.f};
    #pragma unroll
    for (int qt = 0; qt < 7; qt++) {
        #pragma unroll
        for (int t = 0; t < 7; t++) {
            float d = q[qt].x * k[t].x + q[qt].y * k[t].y
                    + q[qt].z * k[t].z + q[qt].w * k[t].w;
            d += __shfl_xor_sync(0xffffffffu, d, 1);
            d += __shfl_xor_sync(0xffffffffu, d, 2);
            d += __shfl_xor_sync(0xffffffffu, d, 4);
            const int p = qt * 7 + t;
            if ((p & 7) == dg) e[p >> 3] = __expf(d * scale);
        }
    }

    float4 ctx[7];
    float den[7];
    #pragma unroll
    for (int qt = 0; qt < 7; qt++) { ctx[qt] = make_float4(0, 0, 0, 0); den[qt] = 0.f; }
    #pragma unroll
    for (int qt = 0; qt < 7; qt++) {
        #pragma unroll
        for (int t = 0; t < 7; t++) {
            const int p = qt * 7 + t;
            float eb = __shfl_sync(0xffffffffu, e[p >> 3], p & 7, 8);
            den[qt] += eb;
            ctx[qt].x += eb * v[t].x;
            ctx[qt].y += eb * v[t].y;
            ctx[qt].z += eb * v[t].z;
            ctx[qt].w += eb * v[t].w;
        }
    }
    #pragma unroll
    for (int qt = 0; qt < 7; qt++) {
        const float r = 1.0f / den[qt];
        float4 o = make_float4(ctx[qt].x * r, ctx[qt].y * r, ctx[qt].z * r, ctx[qt].w * r);
        *reinterpret_cast<uint2*>(g_ctx_h + (size_t)(qt * NTOK + s) * CDIM + col) = f4_to_h4(o);
    }
}

// ---------------------------------------------------------------------------
extern "C" void kernel_launch(void* const* d_in, const int* /*in_sizes*/, int /*n_in*/,
                              void* d_out, int /*out_size*/) {
    const float* frames = (const float*)d_in[0];
    const float* temb   = (const float*)d_in[1];
    const float* Wq     = (const float*)d_in[2];
    const float* bq     = (const float*)d_in[3];
    const float* Wk     = (const float*)d_in[4];
    const float* bk     = (const float*)d_in[5];
    const float* Wv     = (const float*)d_in[6];
    const float* bv     = (const float*)d_in[7];
    const float* Wo     = (const float*)d_in[8];
    const float* bo     = (const float*)d_in[9];
    float* out = (float*)d_out;

    void *p_ah, *p_qkv, *p_ctx, *p_wbt, *p_wot, *p_bias;
    cudaGetSymbolAddress(&p_ah,   g_a_h);
    cudaGetSymbolAddress(&p_qkv,  g_qkv_h);
    cudaGetSymbolAddress(&p_ctx,  g_ctx_h);
    cudaGetSymbolAddress(&p_wbt,  g_wbt_h);
    cudaGetSymbolAddress(&p_wot,  g_wot_h);
    cudaGetSymbolAddress(&p_bias, g_bias);

    cudaFuncSetAttribute(gemm_h_kernel<NQKV, NQKV, true>,
                         cudaFuncAttributeMaxDynamicSharedMemorySize, SM_TOTAL);
    cudaFuncSetAttribute(gemm_h_kernel<CDIM, 0, false>,
                         cudaFuncAttributeMaxDynamicSharedMemorySize, SM_TOTAL);

    prep_wt_kernel<<<(NQKV * CDIM + CDIM * CDIM + 255) / 256, 256>>>(Wq, Wk, Wv, Wo);
    prep_bias_kernel<<<(T_ * NQKV + 255) / 256, 256>>>(temb, Wq, bq, Wk, bk, bv);
    prep_frames_kernel<<<(ROWS * CDIM / 4) / 256, 256>>>(frames);

    // QKV projection: [258048 x 256] @ [256 x 768] + bias[t]  -> fp16 qkv
    gemm_h_kernel<NQKV, NQKV, true><<<dim3(6, ROWS / 128), 128, SM_TOTAL>>>(
        (const __half*)p_ah, (const __half*)p_wbt, (const float*)p_bias, p_qkv);

    // Attention (fp16 -> fp16)
    attn_kernel<<<(NTOK * 2 * 32) / 256, 256>>>();

    // Output projection: [258048 x 256] @ [256 x 256] + bo -> f32 out
    gemm_h_kernel<CDIM, 0, false><<<dim3(2, ROWS / 128), 128, SM_TOTAL>>>(
        (const __half*)p_ctx, (const __half*)p_wot, bo, out);
}

// round 8
// speedup vs baseline: 1.0543x; 1.0409x over previous
#include <cuda_runtime.h>
#include <cuda_fp16.h>
#include <cstdint>

#define T_ 7
#define NTOK 36864            // B*H*W
#define ROWS (T_ * NTOK)      // 258048
#define CDIM 256
#define NQKV 768

// Scratch (device globals — no allocation allowed)
__device__ __half g_a_h[(size_t)ROWS * CDIM];    // frames, fp16
__device__ __half g_qkv_h[(size_t)ROWS * NQKV];  // [t*NTOK+s][q|k|v], fp16
__device__ __half g_ctx_h[(size_t)ROWS * CDIM];  // attn out, fp16
__device__ __half g_wbt_h[NQKV * CDIM];          // [n][k], fp16
__device__ __half g_wot_h[CDIM * CDIM];          // [c][nd], fp16
__device__ float  g_bias[T_ * NQKV];

// ---------------------------------------------------------------------------
// Portable PTX helpers (compute_103 virtual arch — no tcgen05/TMA-tensor)
// ---------------------------------------------------------------------------
__device__ __forceinline__ uint32_t smem_u32(const void* p) {
    uint32_t a;
    asm("{ .reg .u64 t; cvta.to.shared.u64 t, %1; cvt.u32.u64 %0, t; }" : "=r"(a) : "l"(p));
    return a;
}
__device__ __forceinline__ void ldsm4(uint32_t* r, uint32_t addr) {
    asm volatile("ldmatrix.sync.aligned.m8n8.x4.shared.b16 {%0,%1,%2,%3}, [%4];"
        : "=r"(r[0]), "=r"(r[1]), "=r"(r[2]), "=r"(r[3]) : "r"(addr));
}
__device__ __forceinline__ void mma_f16(float* d, const uint32_t* a, const uint32_t* b) {
    asm volatile("mma.sync.aligned.m16n8k16.row.col.f32.f16.f16.f32 "
        "{%0,%1,%2,%3}, {%4,%5,%6,%7}, {%8,%9}, {%0,%1,%2,%3};"
        : "+f"(d[0]), "+f"(d[1]), "+f"(d[2]), "+f"(d[3])
        : "r"(a[0]), "r"(a[1]), "r"(a[2]), "r"(a[3]), "r"(b[0]), "r"(b[1]));
}
#define CP_ASYNC16(dst, src) asm volatile("cp.async.cg.shared.global [%0], [%1], 16;" :: "r"(dst), "l"(src))
#define CP_COMMIT()          asm volatile("cp.async.commit_group;" ::: "memory")
#define CP_WAIT1()           asm volatile("cp.async.wait_group 1;" ::: "memory")
#define CP_WAIT0()           asm volatile("cp.async.wait_group 0;" ::: "memory")

__device__ __forceinline__ uint2 f4_to_h4(float4 v) {
    __half2 h0 = __float22half2_rn(make_float2(v.x, v.y));
    __half2 h1 = __float22half2_rn(make_float2(v.z, v.w));
    uint2 r;
    r.x = *reinterpret_cast<uint32_t*>(&h0);
    r.y = *reinterpret_cast<uint32_t*>(&h1);
    return r;
}
__device__ __forceinline__ float4 h4_to_f4(uint2 u) {
    __half2 h0 = *reinterpret_cast<__half2*>(&u.x);
    __half2 h1 = *reinterpret_cast<__half2*>(&u.y);
    float2 a = __half22float2(h0), b = __half22float2(h1);
    return make_float4(a.x, a.y, b.x, b.y);
}

#define STAGE_BYTES 32768u    // A 16KB (128x64 fp16) + B 16KB (128x64 fp16)
#define SM_TOTAL (3 * STAGE_BYTES)   // 96KB/CTA -> 2 CTAs/SM (192KB < 228KB)

// ---------------------------------------------------------------------------
// Merged prep: frames f32->fp16, weights pack+transpose, t_emb-folded bias.
// Block role by blockIdx.x range (one launch instead of three).
// ---------------------------------------------------------------------------
#define NBLK_FRAMES 64512     // ROWS*CDIM/4/256
#define NBLK_WT     1024      // (NQKV*CDIM + CDIM*CDIM)/256
#define NBLK_BIAS   21        // ceil(T_*NQKV/256)

__global__ void prep_all_kernel(const float* __restrict__ frames,
                                const float* __restrict__ te,
                                const float* __restrict__ Wq,
                                const float* __restrict__ bq,
                                const float* __restrict__ Wk,
                                const float* __restrict__ bk,
                                const float* __restrict__ Wv,
                                const float* __restrict__ bv,
                                const float* __restrict__ Wo) {
    const int bid = blockIdx.x;
    if (bid < NBLK_FRAMES) {
        size_t i = (size_t)bid * 256 + threadIdx.x;     // float4 slot
        const float4 v = reinterpret_cast<const float4*>(frames)[i];
        reinterpret_cast<uint2*>(g_a_h)[i] = f4_to_h4(v);
    } else if (bid < NBLK_FRAMES + NBLK_WT) {
        int i = (bid - NBLK_FRAMES) * 256 + threadIdx.x;
        if (i < NQKV * CDIM) {
            int n = i / CDIM, c = i % CDIM;
            float v;
            if (n < 256)      v = Wq[c * 256 + n];
            else if (n < 512) v = Wk[c * 256 + (n - 256)];
            else              v = Wv[c * 256 + (n - 512)];
            g_wbt_h[i] = __float2half_rn(v);
        } else {
            int j = i - NQKV * CDIM;
            int co = j / CDIM, nd = j % CDIM;
            g_wot_h[j] = __float2half_rn(Wo[nd * 256 + co]);
        }
    } else {
        int i = (bid - NBLK_FRAMES - NBLK_WT) * 256 + threadIdx.x;
        if (i >= T_ * NQKV) return;
        int t = i / NQKV, n = i % NQKV;
        float r;
        if (n < 512) {
            const float* W = (n < 256) ? Wq : Wk;
            int nn = n & 255;
            float acc = (n < 256) ? bq[nn] : bk[nn];
            for (int c = 0; c < CDIM; c++) acc += te[t * CDIM + c] * W[c * 256 + nn];
            r = acc;
        } else {
            r = bv[n - 512];
        }
        g_bias[i] = r;
    }
}

// ---------------------------------------------------------------------------
// fp16 mma.sync GEMM: C[row][n] = A[row][k] * Bt[n][k] + bias
// CTA 128(M) x 128(N), K=256 in 4 chunks of 64, 3-stage cp.async pipeline.
// 8 warps, warp tile 32x64 (2m x 8n of m16n8k16).
// __launch_bounds__(256,2): 2 CTAs/SM. Next-stage cp.async issued BEFORE the
// compute block (buffer (kc+2)%3 was last read at kc-1; barrier makes it safe)
// so DRAM loads overlap the whole chunk's compute.
// ---------------------------------------------------------------------------
template<int NW, int TSTRIDE, bool OUT_HALF>
__global__ __launch_bounds__(256, 2)
void gemm_h_kernel(const __half* __restrict__ A,
                   const __half* __restrict__ Bt,
                   const float* __restrict__ bias,
                   void* __restrict__ Cout) {
    extern __shared__ __align__(128) char smem[];
    const uint32_t sb = smem_u32(smem);

    const int tid  = threadIdx.x;
    const int lane = tid & 31, wid = tid >> 5;
    const int wm = wid >> 1;          // 0..3 : rows wm*32
    const int wn = wid & 1;           // 0..1 : cols wn*64
    const int row0 = blockIdx.y * 128;
    const int col0 = blockIdx.x * 128;

    // Fragment addressing (SW128 xor; smem rows are 64 fp16 = 128B)
    const uint32_t fxor  = (uint32_t)(lane & 7) << 4;
    const uint32_t a_row = (uint32_t)(wm * 32 + (lane & 15)) * 128;
    const uint32_t ahalf = (uint32_t)(lane >> 4) * 16;
    const uint32_t b_row = (uint32_t)(wn * 64 + (lane & 7) + ((lane >> 4) << 3)) * 128;
    const uint32_t bhalf = (uint32_t)((lane >> 3) & 1) * 16;

    auto stageA = [&](int kc, uint32_t nb) {
        #pragma unroll
        for (int i = 0; i < 4; i++) {
            int g = tid + i * 256;                 // 1024 granules (128 rows x 8)
            int r = g >> 3, c16 = g & 7;
            uint32_t dst = nb + (uint32_t)r * 128 + (((uint32_t)c16 * 16) ^ (((uint32_t)(r & 7)) << 4));
            const __half* src = A + (size_t)(row0 + r) * CDIM + kc * 64 + c16 * 8;
            CP_ASYNC16(dst, src);
        }
    };
    auto stageB = [&](int kc, uint32_t nb) {
        #pragma unroll
        for (int i = 0; i < 4; i++) {
            int g = tid + i * 256;                 // 1024 granules (128 rows x 8)
            int r = g >> 3, c16 = g & 7;
            uint32_t dst = nb + 16384u + (uint32_t)r * 128 + (((uint32_t)c16 * 16) ^ (((uint32_t)(r & 7)) << 4));
            const __half* src = Bt + (size_t)(col0 + r) * CDIM + kc * 64 + c16 * 8;
            CP_ASYNC16(dst, src);
        }
    };

    // prologue: stage chunks 0, 1
    stageA(0, sb);               stageB(0, sb);               CP_COMMIT();
    stageA(1, sb + STAGE_BYTES); stageB(1, sb + STAGE_BYTES); CP_COMMIT();

    float acc[2][8][4];
    #pragma unroll
    for (int mt = 0; mt < 2; mt++)
        #pragma unroll
        for (int nt = 0; nt < 8; nt++)
            #pragma unroll
            for (int e = 0; e < 4; e++) acc[mt][nt][e] = 0.0f;

    #pragma unroll 1
    for (int kc = 0; kc < 4; kc++) {
        const uint32_t sbase = sb + (uint32_t)(kc % 3) * STAGE_BYTES;
        if (kc == 3) { CP_WAIT0(); } else { CP_WAIT1(); }
        __syncthreads();

        // Issue next stage FIRST so its DRAM latency overlaps this chunk's mma.
        if (kc < 2) {
            const uint32_t nb = sb + (uint32_t)((kc + 2) % 3) * STAGE_BYTES;
            stageA(kc + 2, nb);
            stageB(kc + 2, nb);
            CP_COMMIT();
        }

        #pragma unroll
        for (int ks = 0; ks < 4; ks++) {
            uint32_t af[2][4];
            #pragma unroll
            for (int mt = 0; mt < 2; mt++)
                ldsm4(af[mt], sbase + a_row + (uint32_t)mt * 2048 + ((ahalf + ks * 32) ^ fxor));
            uint32_t bf[4][4];
            #pragma unroll
            for (int np = 0; np < 4; np++)
                ldsm4(bf[np], sbase + 16384u + b_row + (uint32_t)np * 2048 + ((bhalf + ks * 32) ^ fxor));
            #pragma unroll
            for (int mt = 0; mt < 2; mt++)
                #pragma unroll
                for (int nt = 0; nt < 8; nt++)
                    mma_f16(acc[mt][nt], af[mt], &bf[nt >> 1][(nt & 1) * 2]);
        }
    }
    __syncthreads();

    // epilogue: frags -> smem f32 -> coalesced global (+bias)
    float* Cs = reinterpret_cast<float*>(smem);    // [128][132] = 67.6KB
    #pragma unroll
    for (int mt = 0; mt < 2; mt++) {
        const int r0 = wm * 32 + mt * 16 + (lane >> 2);
        #pragma unroll
        for (int nt = 0; nt < 8; nt++) {
            const int c0 = wn * 64 + nt * 8 + (lane & 3) * 2;
            *reinterpret_cast<float2*>(Cs + r0 * 132 + c0)       = make_float2(acc[mt][nt][0], acc[mt][nt][1]);
            *reinterpret_cast<float2*>(Cs + (r0 + 8) * 132 + c0) = make_float2(acc[mt][nt][2], acc[mt][nt][3]);
        }
    }
    __syncthreads();

    const int t = TSTRIDE ? (blockIdx.y / 288) : 0;
    #pragma unroll
    for (int i = 0; i < 16; i++) {
        int id = tid + i * 256;                    // 4096 float4 slots
        int r = id >> 5, c = (id & 31) * 4;
        float4 v = *reinterpret_cast<const float4*>(Cs + r * 132 + c);
        int n = col0 + c;
        const float4 b4 = *reinterpret_cast<const float4*>(bias + t * TSTRIDE + n);
        v.x += b4.x; v.y += b4.y; v.z += b4.z; v.w += b4.w;
        if (OUT_HALF) {
            *reinterpret_cast<uint2*>(reinterpret_cast<__half*>(Cout) + (size_t)(row0 + r) * NW + n) = f4_to_h4(v);
        } else {
            *reinterpret_cast<float4*>(reinterpret_cast<float*>(Cout) + (size_t)(row0 + r) * NW + n) = v;
        }
    }
}

// ---------------------------------------------------------------------------
// Attention over T=7 per (token, 4-head group), fp16 in / fp16 out.
// ---------------------------------------------------------------------------
__global__ void attn_kernel() {
    const int gw = (blockIdx.x * blockDim.x + threadIdx.x) >> 5;
    const int lane = threadIdx.x & 31;
    const int s = gw >> 1;
    const int half = gw & 1;
    const int hg = lane >> 3, dg = lane & 7;
    const int col = (half * 4 + hg) * 32 + dg * 4;

    float4 q[7], k[7], v[7];
    #pragma unroll
    for (int t = 0; t < 7; t++) {
        const __half* base = g_qkv_h + (size_t)(t * NTOK + s) * NQKV;
        q[t] = h4_to_f4(*reinterpret_cast<const uint2*>(base + col));
        k[t] = h4_to_f4(*reinterpret_cast<const uint2*>(base + 256 + col));
        v[t] = h4_to_f4(*reinterpret_cast<const uint2*>(base + 512 + col));
    }

    const float scale = 0.17677669529663687f;  // 1/sqrt(32)
    float e[7] = {0.f, 0.f, 0.f, 0.f, 0.f, 0.f, 0.f};
    #pragma unroll
    for (int qt = 0; qt < 7; qt++) {
        #pragma unroll
        for (int t = 0; t < 7; t++) {
            float d = q[qt].x * k[t].x + q[qt].y * k[t].y
                    + q[qt].z * k[t].z + q[qt].w * k[t].w;
            d += __shfl_xor_sync(0xffffffffu, d, 1);
            d += __shfl_xor_sync(0xffffffffu, d, 2);
            d += __shfl_xor_sync(0xffffffffu, d, 4);
            const int p = qt * 7 + t;
            if ((p & 7) == dg) e[p >> 3] = __expf(d * scale);
        }
    }

    float4 ctx[7];
    float den[7];
    #pragma unroll
    for (int qt = 0; qt < 7; qt++) { ctx[qt] = make_float4(0, 0, 0, 0); den[qt] = 0.f; }
    #pragma unroll
    for (int qt = 0; qt < 7; qt++) {
        #pragma unroll
        for (int t = 0; t < 7; t++) {
            const int p = qt * 7 + t;
            float eb = __shfl_sync(0xffffffffu, e[p >> 3], p & 7, 8);
            den[qt] += eb;
            ctx[qt].x += eb * v[t].x;
            ctx[qt].y += eb * v[t].y;
            ctx[qt].z += eb * v[t].z;
            ctx[qt].w += eb * v[t].w;
        }
    }
    #pragma unroll
    for (int qt = 0; qt < 7; qt++) {
        const float r = 1.0f / den[qt];
        float4 o = make_float4(ctx[qt].x * r, ctx[qt].y * r, ctx[qt].z * r, ctx[qt].w * r);
        *reinterpret_cast<uint2*>(g_ctx_h + (size_t)(qt * NTOK + s) * CDIM + col) = f4_to_h4(o);
    }
}

// ---------------------------------------------------------------------------
extern "C" void kernel_launch(void* const* d_in, const int* /*in_sizes*/, int /*n_in*/,
                              void* d_out, int /*out_size*/) {
    const float* frames = (const float*)d_in[0];
    const float* temb   = (const float*)d_in[1];
    const float* Wq     = (const float*)d_in[2];
    const float* bq     = (const float*)d_in[3];
    const float* Wk     = (const float*)d_in[4];
    const float* bk     = (const float*)d_in[5];
    const float* Wv     = (const float*)d_in[6];
    const float* bv     = (const float*)d_in[7];
    const float* Wo     = (const float*)d_in[8];
    const float* bo     = (const float*)d_in[9];
    float* out = (float*)d_out;

    void *p_ah, *p_qkv, *p_ctx, *p_wbt, *p_wot, *p_bias;
    cudaGetSymbolAddress(&p_ah,   g_a_h);
    cudaGetSymbolAddress(&p_qkv,  g_qkv_h);
    cudaGetSymbolAddress(&p_ctx,  g_ctx_h);
    cudaGetSymbolAddress(&p_wbt,  g_wbt_h);
    cudaGetSymbolAddress(&p_wot,  g_wot_h);
    cudaGetSymbolAddress(&p_bias, g_bias);

    cudaFuncSetAttribute(gemm_h_kernel<NQKV, NQKV, true>,
                         cudaFuncAttributeMaxDynamicSharedMemorySize, SM_TOTAL);
    cudaFuncSetAttribute(gemm_h_kernel<CDIM, 0, false>,
                         cudaFuncAttributeMaxDynamicSharedMemorySize, SM_TOTAL);

    // Single prep launch: frames->fp16, weight pack, bias fold
    prep_all_kernel<<<NBLK_FRAMES + NBLK_WT + NBLK_BIAS, 256>>>(
        frames, temb, Wq, bq, Wk, bk, Wv, bv, Wo);

    // QKV projection: [258048 x 256] @ [256 x 768] + bias[t]  -> fp16 qkv
    gemm_h_kernel<NQKV, NQKV, true><<<dim3(6, ROWS / 128), 256, SM_TOTAL>>>(
        (const __half*)p_ah, (const __half*)p_wbt, (const float*)p_bias, p_qkv);

    // Attention (fp16 -> fp16)
    attn_kernel<<<(NTOK * 2 * 32) / 256, 256>>>();

    // Output projection: [258048 x 256] @ [256 x 256] + bo -> f32 out
    gemm_h_kernel<CDIM, 0, false><<<dim3(2, ROWS / 128), 256, SM_TOTAL>>>(
        (const __half*)p_ctx, (const __half*)p_wot, bo, out);
}